// round 4
// baseline (speedup 1.0000x reference)
#include <cuda_runtime.h>

#define BS   2
#define SEQ  2048
#define DIM  1024
#define NH   16
#define HD   64
#define PREFIX 256
#define MROWS (BS*SEQ)

// Scratch (allocation-free rule: __device__ globals).
// NOTE: these symbols are ONLY referenced from device code. Referencing them
// from host code (e.g. passing as a kernel argument) yields the host shadow
// address — which GB300's ATS will happily read as zeros. That was the
// rounds-1..3 bug.
__device__ float g_Q[BS*NH*SEQ*HD];
__device__ float g_K[BS*NH*SEQ*HD];
__device__ float g_V[BS*NH*SEQ*HD];
__device__ float g_O[MROWS*DIM];

// ---------------------------------------------------------------------------
// GEMM: C = A(M,K) @ W(N,K)^T   (both row-major, K contiguous)
// 128x128 block tile, BK=16, 256 threads, 8x8 per thread.
// WHICH==0: A comes from param (x), scatter into g_Q/g_K/g_V (Q pre-scaled)
// WHICH==1: A is the device symbol g_O, write Cout row-major with bias
// ---------------------------------------------------------------------------
template<int WHICH>
__global__ __launch_bounds__(256) void gemm_kernel(const float* __restrict__ A,
                                                   const float* __restrict__ W,
                                                   const float* __restrict__ bias,
                                                   float* __restrict__ Cout)
{
    const int K = DIM;
    __shared__ float As[16][132];
    __shared__ float Bs[16][132];

    int tid = threadIdx.x;
    int tm  = tid >> 4;
    int tn  = tid & 15;
    int bm  = blockIdx.y;
    int bn  = blockIdx.x;

    float acc[8][8];
#pragma unroll
    for (int i = 0; i < 8; i++)
#pragma unroll
        for (int j = 0; j < 8; j++) acc[i][j] = 0.f;

    // resolve A in DEVICE code so g_O gets the real device address
    const float* Abase = (WHICH == 1) ? (const float*)g_O : A;
    const float* Ab = Abase + (size_t)bm * 128 * K;
    const float* Wb = W + (size_t)bn * 128 * K;

    for (int k0 = 0; k0 < K; k0 += 16) {
#pragma unroll
        for (int i = 0; i < 2; i++) {
            int f   = tid + i * 256;       // 0..511 over 128 rows x 4 float4
            int row = f >> 2;
            int kq  = (f & 3) << 2;
            float4 va = *(const float4*)(Ab + (size_t)row * K + k0 + kq);
            As[kq+0][row] = va.x; As[kq+1][row] = va.y;
            As[kq+2][row] = va.z; As[kq+3][row] = va.w;
            float4 vb = *(const float4*)(Wb + (size_t)row * K + k0 + kq);
            Bs[kq+0][row] = vb.x; Bs[kq+1][row] = vb.y;
            Bs[kq+2][row] = vb.z; Bs[kq+3][row] = vb.w;
        }
        __syncthreads();

#pragma unroll
        for (int kk = 0; kk < 16; kk++) {
            float a[8], b[8];
            *(float4*)(a)   = *(const float4*)&As[kk][tm*8];
            *(float4*)(a+4) = *(const float4*)&As[kk][tm*8+4];
            *(float4*)(b)   = *(const float4*)&Bs[kk][tn*8];
            *(float4*)(b+4) = *(const float4*)&Bs[kk][tn*8+4];
#pragma unroll
            for (int i = 0; i < 8; i++)
#pragma unroll
                for (int j = 0; j < 8; j++) acc[i][j] += a[i] * b[j];
        }
        __syncthreads();
    }

    int mbase = bm * 128 + tm * 8;
    int nbase = bn * 128 + tn * 8;

    if (WHICH == 0) {
        // whole block column lies in one of q/k/v (128 | 1024)
        int part = (bn * 128) >> 10;
        float* dst = (part == 0) ? g_Q : (part == 1) ? g_K : g_V;
        float scl  = (part == 0) ? 0.125f : 1.0f;   // 1/sqrt(hd)
#pragma unroll
        for (int i = 0; i < 8; i++) {
            int m    = mbase + i;
            int b    = m >> 11;           // m / SEQ
            int srow = m & (SEQ - 1);
#pragma unroll
            for (int jv = 0; jv < 2; jv++) {
                int n    = nbase + jv * 4;
                int head = (n & 1023) >> 6;
                int d    = n & 63;
                float4 v = make_float4(acc[i][jv*4+0]*scl, acc[i][jv*4+1]*scl,
                                       acc[i][jv*4+2]*scl, acc[i][jv*4+3]*scl);
                *(float4*)&dst[(((size_t)(b*NH + head))*SEQ + srow)*HD + d] = v;
            }
        }
    } else {
#pragma unroll
        for (int i = 0; i < 8; i++) {
            int m = mbase + i;
#pragma unroll
            for (int jv = 0; jv < 2; jv++) {
                int n = nbase + jv * 4;
                float4 v = make_float4(acc[i][jv*4+0] + bias[n+0],
                                       acc[i][jv*4+1] + bias[n+1],
                                       acc[i][jv*4+2] + bias[n+2],
                                       acc[i][jv*4+3] + bias[n+3]);
                *(float4*)&Cout[(size_t)m * DIM + n] = v;
            }
        }
    }
}

// ---------------------------------------------------------------------------
// Flash attention: one block = 64 queries of one (b,h). Streams 32-key tiles.
// STATIC shared memory only (43,520 B < 48 KB).
// 256 threads as 16x16: thread (ty,tx) owns 4 queries (ty*4..) and, for S,
// 2 keys (tx*2..); for PV, 4 output dims (tx*4..).
// Mask is DATA-INDEPENDENT: allowed(q,k) = (k <= q) || (k < 256). Per 32-key
// tile, masking is needed only when kbase >= 256 and kbase+31 > qbase.
// Q was pre-scaled by 1/8 in the QKV epilogue.
// ---------------------------------------------------------------------------
__global__ __launch_bounds__(256) void attn_kernel()
{
    __shared__ __align__(16) float Qt[64][68];   // Qt[d][q]  17408 B
    __shared__ __align__(16) float Kt[64][34];   // Kt[d][k]   8704 B
    __shared__ __align__(16) float Vs[32][68];   // Vs[k][d]   8704 B
    __shared__ __align__(16) float Pt[32][68];   // Pt[k][q]   8704 B

    int qi = blockIdx.x;             // 0..31 query tiles (64 queries each)
    int bh = blockIdx.y;             // 0..31 (b*16+h)
    int b  = bh >> 4;
    int h  = bh & 15;
    int tid = threadIdx.x;
    int ty  = tid >> 4;
    int tx  = tid & 15;

    const float* Qp = g_Q + (size_t)bh * SEQ * HD;
    const float* Kp = g_K + (size_t)bh * SEQ * HD;
    const float* Vp = g_V + (size_t)bh * SEQ * HD;

    int qbase = qi * 64;

    // load Q tile transposed: Qt[d][r]
    for (int i = tid; i < 64 * 16; i += 256) {
        int r  = i >> 4;
        int d4 = (i & 15) << 2;
        float4 v = *(const float4*)(Qp + (size_t)(qbase + r) * HD + d4);
        Qt[d4+0][r] = v.x; Qt[d4+1][r] = v.y;
        Qt[d4+2][r] = v.z; Qt[d4+3][r] = v.w;
    }

    float mi[4], li[4], acc[4][4];
#pragma unroll
    for (int r = 0; r < 4; r++) {
        mi[r] = -1e30f; li[r] = 0.f;
#pragma unroll
        for (int c = 0; c < 4; c++) acc[r][c] = 0.f;
    }

    // keys visible to this query tile: max(PREFIX, (qi+1)*64), in 32-key tiles
    int ntiles = (qi < 4) ? 8 : 2 * (qi + 1);

    for (int j = 0; j < ntiles; j++) {
        __syncthreads();                 // prev PV done before overwriting K/V
        int kbase = j * 32;

        // load K transposed (Kt[d][c]) and V row-major (Vs[c][d])
        for (int i = tid; i < 32 * 16; i += 256) {
            int r  = i >> 4;             // 0..31
            int d4 = (i & 15) << 2;
            float4 kv = *(const float4*)(Kp + (size_t)(kbase + r) * HD + d4);
            Kt[d4+0][r] = kv.x; Kt[d4+1][r] = kv.y;
            Kt[d4+2][r] = kv.z; Kt[d4+3][r] = kv.w;
            float4 vv = *(const float4*)(Vp + (size_t)(kbase + r) * HD + d4);
            *(float4*)&Vs[r][d4] = vv;
        }
        __syncthreads();

        // S = Q K^T : 4 queries x 2 keys per thread
        float s[4][2];
#pragma unroll
        for (int r = 0; r < 4; r++) { s[r][0] = 0.f; s[r][1] = 0.f; }

#pragma unroll 8
        for (int d = 0; d < 64; d++) {
            float qa[4], kb[2];
            *(float4*)qa = *(const float4*)&Qt[d][ty*4];
            *(float2*)kb = *(const float2*)&Kt[d][tx*2];
#pragma unroll
            for (int r = 0; r < 4; r++) {
                s[r][0] += qa[r] * kb[0];
                s[r][1] += qa[r] * kb[1];
            }
        }

        // causal mask: only needed outside the prefix on near-diagonal tiles
        if (kbase >= PREFIX && kbase + 31 > qbase) {
#pragma unroll
            for (int r = 0; r < 4; r++) {
                int qq = qbase + ty * 4 + r;
#pragma unroll
                for (int c = 0; c < 2; c++) {
                    int kk = kbase + tx * 2 + c;
                    if (kk > qq) s[r][c] = -1e30f;
                }
            }
        }

        // online softmax + write P^T
#pragma unroll
        for (int r = 0; r < 4; r++) {
            float mx = fmaxf(s[r][0], s[r][1]);
#pragma unroll
            for (int o = 1; o < 16; o <<= 1)
                mx = fmaxf(mx, __shfl_xor_sync(0xffffffffu, mx, o));
            float mnew  = fmaxf(mi[r], mx);
            float alpha = __expf(mi[r] - mnew);
            float p0 = __expf(s[r][0] - mnew);
            float p1 = __expf(s[r][1] - mnew);
            float rs = p0 + p1;
#pragma unroll
            for (int o = 1; o < 16; o <<= 1)
                rs += __shfl_xor_sync(0xffffffffu, rs, o);
            li[r] = li[r] * alpha + rs;
            mi[r] = mnew;
#pragma unroll
            for (int c = 0; c < 4; c++) acc[r][c] *= alpha;
            Pt[tx*2 + 0][ty*4 + r] = p0;
            Pt[tx*2 + 1][ty*4 + r] = p1;
        }
        __syncthreads();

        // O += P V : 4 queries x 4 dims per thread
#pragma unroll 8
        for (int c2 = 0; c2 < 32; c2++) {
            float pa[4], vb[4];
            *(float4*)pa = *(const float4*)&Pt[c2][ty*4];
            *(float4*)vb = *(const float4*)&Vs[c2][tx*4];
#pragma unroll
            for (int r = 0; r < 4; r++)
#pragma unroll
                for (int c = 0; c < 4; c++) acc[r][c] += pa[r] * vb[c];
        }
    }

    // normalize and write O in [b][s][h*64+d] layout for the proj GEMM
#pragma unroll
    for (int r = 0; r < 4; r++) {
        float inv  = 1.0f / li[r];
        int   srow = qbase + ty * 4 + r;
        float4 o = make_float4(acc[r][0]*inv, acc[r][1]*inv,
                               acc[r][2]*inv, acc[r][3]*inv);
        *(float4*)&g_O[((size_t)(b*SEQ + srow))*DIM + h*HD + tx*4] = o;
    }
}

// ---------------------------------------------------------------------------
extern "C" void kernel_launch(void* const* d_in, const int* in_sizes, int n_in,
                              void* d_out, int out_size)
{
    const float* x      = (const float*)d_in[0];
    const float* qkv_w  = (const float*)d_in[1];
    const float* proj_w = (const float*)d_in[2];
    const float* proj_b = (const float*)d_in[3];
    float*       out    = (float*)d_out;

    // 1) QKV projection: (4096 x 1024) @ (1024 x 3072)
    gemm_kernel<0><<<dim3(3*DIM/128, MROWS/128), 256>>>(x, qkv_w, nullptr, nullptr);

    // 2) flash attention over (32 q-tiles) x (32 batch-heads), static smem only
    attn_kernel<<<dim3(SEQ/64, BS*NH), 256>>>();

    // 3) output projection + bias (A = g_O resolved in device code)
    gemm_kernel<1><<<dim3(DIM/128, MROWS/128), 256>>>(nullptr, proj_w, proj_b, out);
}

// round 6
// speedup vs baseline: 1.3015x; 1.3015x over previous
#include <cuda_runtime.h>
#include <cuda_bf16.h>
#include <cstdint>

#define BS   2
#define SEQ  2048
#define DIM  1024
#define NH   16
#define HD   64
#define PREFIX 256
#define MROWS (BS*SEQ)
#define KT   (3*DIM)          // tripled K for bf16-split GEMM

// ------------------------- device scratch (no allocs) -----------------------
__device__ float g_Q[BS*NH*SEQ*HD];
__device__ float g_K[BS*NH*SEQ*HD];
__device__ float g_V[BS*NH*SEQ*HD];
__device__ float g_O[MROWS*DIM];
__device__ __nv_bfloat16 g_x3 [MROWS*KT];      // x split-3      (4096 x 3072)
__device__ __nv_bfloat16 g_w3 [3*DIM*KT];      // qkv_w split-3  (3072 x 3072)
__device__ __nv_bfloat16 g_o3 [MROWS*KT];      // attn out split (4096 x 3072)
__device__ __nv_bfloat16 g_pw3[DIM*KT];        // proj_w split-3 (1024 x 3072)

// ------------------------- portable PTX helpers (sm_80+) --------------------
__device__ __forceinline__ uint32_t smem_u32(const void* p) {
    uint32_t a;
    asm("{ .reg .u64 t; cvta.to.shared.u64 t, %1; cvt.u32.u64 %0, t; }" : "=r"(a) : "l"(p));
    return a;
}
__device__ __forceinline__ void cp16(uint32_t saddr, const void* g) {
    asm volatile("cp.async.cg.shared.global [%0], [%1], 16;" :: "r"(saddr), "l"(g));
}
#define CP_COMMIT()  asm volatile("cp.async.commit_group;" ::: "memory")
#define CP_WAIT(n)   asm volatile("cp.async.wait_group %0;" :: "n"(n) : "memory")

__device__ __forceinline__ void ldsm4(uint32_t* r, uint32_t addr) {
    asm volatile("ldmatrix.sync.aligned.m8n8.x4.shared.b16 {%0,%1,%2,%3}, [%4];"
                 : "=r"(r[0]), "=r"(r[1]), "=r"(r[2]), "=r"(r[3]) : "r"(addr));
}
__device__ __forceinline__ void mma16816(float* c, const uint32_t* a, uint32_t b0, uint32_t b1) {
    asm volatile("mma.sync.aligned.m16n8k16.row.col.f32.bf16.bf16.f32 "
                 "{%0,%1,%2,%3}, {%4,%5,%6,%7}, {%8,%9}, {%0,%1,%2,%3};"
                 : "+f"(c[0]), "+f"(c[1]), "+f"(c[2]), "+f"(c[3])
                 : "r"(a[0]), "r"(a[1]), "r"(a[2]), "r"(a[3]), "r"(b0), "r"(b1));
}

// ---------------------------------------------------------------------------
// split-3 conversion: fp32 -> bf16 triplets.
// MODE 0 (A side): [hi, lo, hi]   MODE 1 (B side): [hi, hi, lo]
// A3 . B3 over 3K  =  hiA*hiB + loA*hiB + hiA*loB  (drops only lo*lo ~ 2^-18)
// ---------------------------------------------------------------------------
template<int MODE>
__global__ __launch_bounds__(256) void split3_kernel(const float* __restrict__ src,
                                                     __nv_bfloat16* __restrict__ dst,
                                                     int n4)
{
    int i = blockIdx.x * blockDim.x + threadIdx.x;
    if (i >= n4) return;
    float4 v = ((const float4*)src)[i];
    float xs[4] = {v.x, v.y, v.z, v.w};
    __nv_bfloat16 t[12];
#pragma unroll
    for (int j = 0; j < 4; j++) {
        __nv_bfloat16 hi = __float2bfloat16(xs[j]);
        __nv_bfloat16 lo = __float2bfloat16(xs[j] - __bfloat162float(hi));
        t[3*j+0] = hi;
        t[3*j+1] = (MODE == 0) ? lo : hi;
        t[3*j+2] = (MODE == 0) ? hi : lo;
    }
    uint2* dp = (uint2*)(dst + (size_t)i * 12);
    const uint2* tp = (const uint2*)t;
    dp[0] = tp[0]; dp[1] = tp[1]; dp[2] = tp[2];
}

// ---------------------------------------------------------------------------
// HMMA bf16 GEMM: C(128x128 per CTA) = A3(M,KT) . B3(N,KT)^T, fp32 accum.
// 8 warps: warp (wm, wn) owns 64x32. m16n8k16 fragments via ldmatrix.x4 from
// 80B-stride smem rows (conflict-free). K-chunk 32, cp.async double buffer.
// EPI 0: scatter to g_Q/g_K/g_V (Q * 0.125)   EPI 1: out = C + bias
// ---------------------------------------------------------------------------
template<int EPI>
__global__ __launch_bounds__(256) void mma_gemm(const __nv_bfloat16* __restrict__ A3,
                                                const __nv_bfloat16* __restrict__ B3,
                                                const float* __restrict__ bias,
                                                float* __restrict__ Cout)
{
    __shared__ __align__(16) __nv_bfloat16 sA[2][128*40];   // 80B row stride
    __shared__ __align__(16) __nv_bfloat16 sB[2][128*40];

    const int tid  = threadIdx.x;
    const int wid  = tid >> 5, lane = tid & 31;
    const int wm   = wid & 1,  wn   = wid >> 1;      // 2x4 warp grid
    const int bn   = blockIdx.x, bm = blockIdx.y;
    const int NCH  = KT / 32;                        // 96 chunks

    const char* Ab = (const char*)(A3 + (size_t)bm * 128 * KT);
    const char* Bb = (const char*)(B3 + (size_t)bn * 128 * KT);

    const uint32_t sA0 = smem_u32(&sA[0][0]);
    const uint32_t sB0 = smem_u32(&sB[0][0]);
    const uint32_t BUFB = 128 * 40 * 2;              // bytes per buffer

    float acc[4][4][4];
#pragma unroll
    for (int i = 0; i < 4; i++)
#pragma unroll
        for (int j = 0; j < 4; j++)
#pragma unroll
            for (int k = 0; k < 4; k++) acc[i][j][k] = 0.f;

    // per-thread load slots: 2 x 16B per operand tile
    const int row0 = tid >> 1;                       // 0..127 (tid, tid+256 -> rows tid>>2? see below)
    // idx = tid + i*256; row = idx>>2, seg = idx&3
#define LOAD_TILE(c, buf)                                                          \
    {                                                                              \
        int koff = (c) * 64;                                                       \
        _Pragma("unroll")                                                          \
        for (int i = 0; i < 2; i++) {                                              \
            int idx = tid + i * 256;                                               \
            int row = idx >> 2, seg = idx & 3;                                     \
            uint32_t so = (uint32_t)(row * 80 + seg * 16 + (buf) * BUFB);          \
            cp16(sA0 + so, Ab + (size_t)row * (KT*2) + koff + seg * 16);           \
            cp16(sB0 + so, Bb + (size_t)row * (KT*2) + koff + seg * 16);           \
        }                                                                          \
    }

    LOAD_TILE(0, 0);
    CP_COMMIT();

    const int lrow = lane & 15;
    const int lcol = (lane >> 4) * 16;

    for (int c = 0; c < NCH; c++) {
        if (c + 1 < NCH) {
            LOAD_TILE(c + 1, (c + 1) & 1);
            CP_COMMIT();
            CP_WAIT(1);
        } else {
            CP_WAIT(0);
        }
        __syncthreads();

        uint32_t abase = sA0 + (c & 1) * BUFB;
        uint32_t bbase = sB0 + (c & 1) * BUFB;
#pragma unroll
        for (int kg = 0; kg < 2; kg++) {
            uint32_t a[4][4], b[2][4];
#pragma unroll
            for (int mt = 0; mt < 4; mt++)
                ldsm4(a[mt], abase + (uint32_t)((wm*64 + mt*16 + lrow) * 80 + kg*32 + lcol));
#pragma unroll
            for (int p = 0; p < 2; p++)
                ldsm4(b[p], bbase + (uint32_t)((wn*32 + p*16 + lrow) * 80 + kg*32 + lcol));
#pragma unroll
            for (int mt = 0; mt < 4; mt++)
#pragma unroll
                for (int nt = 0; nt < 4; nt++) {
                    int p = nt >> 1, q = nt & 1;
                    mma16816(acc[mt][nt], a[mt], b[p][q], b[p][q + 2]);
                }
        }
        __syncthreads();   // compute(c) done before buffer c&1 is overwritten
    }

    // epilogue: thread holds C[m0 + {0,8}][n0 + {0,1}] per (mt, nt)
#pragma unroll
    for (int mt = 0; mt < 4; mt++) {
#pragma unroll
        for (int nt = 0; nt < 4; nt++) {
            int m0 = bm * 128 + wm * 64 + mt * 16 + (lane >> 2);
            int n0 = bn * 128 + wn * 32 + nt * 8 + 2 * (lane & 3);
            float c0 = acc[mt][nt][0], c1 = acc[mt][nt][1];
            float c2 = acc[mt][nt][2], c3 = acc[mt][nt][3];
            if (EPI == 0) {
                int part = n0 >> 10;
                float* dst = (part == 0) ? g_Q : (part == 1) ? g_K : g_V;
                float scl  = (part == 0) ? 0.125f : 1.0f;
                int head = (n0 & 1023) >> 6, d = n0 & 63;
                int b0i = m0 >> 11, s0 = m0 & (SEQ - 1);
                *(float2*)&dst[(((size_t)(b0i*NH + head))*SEQ + s0)*HD + d] =
                    make_float2(c0 * scl, c1 * scl);
                int m1 = m0 + 8;
                int b1i = m1 >> 11, s1 = m1 & (SEQ - 1);
                *(float2*)&dst[(((size_t)(b1i*NH + head))*SEQ + s1)*HD + d] =
                    make_float2(c2 * scl, c3 * scl);
            } else {
                float2 bv = *(const float2*)&bias[n0];
                *(float2*)&Cout[(size_t)m0 * DIM + n0]       = make_float2(c0 + bv.x, c1 + bv.y);
                *(float2*)&Cout[(size_t)(m0 + 8) * DIM + n0] = make_float2(c2 + bv.x, c3 + bv.y);
            }
        }
    }
}

// ---------------------------------------------------------------------------
// Flash attention (unchanged, known-good): fp32, static smem 43.5KB.
// allowed(q,k) = (k <= q) || (k < 256); Q pre-scaled by 1/8 in QKV epilogue.
// ---------------------------------------------------------------------------
__global__ __launch_bounds__(256) void attn_kernel()
{
    __shared__ __align__(16) float Qt[64][68];
    __shared__ __align__(16) float Kt[64][34];
    __shared__ __align__(16) float Vs[32][68];
    __shared__ __align__(16) float Pt[32][68];

    int qi = blockIdx.x, bh = blockIdx.y;
    int b = bh >> 4, h = bh & 15;
    int tid = threadIdx.x, ty = tid >> 4, tx = tid & 15;

    const float* Qp = g_Q + (size_t)bh * SEQ * HD;
    const float* Kp = g_K + (size_t)bh * SEQ * HD;
    const float* Vp = g_V + (size_t)bh * SEQ * HD;
    int qbase = qi * 64;

    for (int i = tid; i < 64 * 16; i += 256) {
        int r = i >> 4, d4 = (i & 15) << 2;
        float4 v = *(const float4*)(Qp + (size_t)(qbase + r) * HD + d4);
        Qt[d4+0][r] = v.x; Qt[d4+1][r] = v.y; Qt[d4+2][r] = v.z; Qt[d4+3][r] = v.w;
    }

    float mi[4], li[4], acc[4][4];
#pragma unroll
    for (int r = 0; r < 4; r++) {
        mi[r] = -1e30f; li[r] = 0.f;
#pragma unroll
        for (int c = 0; c < 4; c++) acc[r][c] = 0.f;
    }

    int ntiles = (qi < 4) ? 8 : 2 * (qi + 1);

    for (int j = 0; j < ntiles; j++) {
        __syncthreads();
        int kbase = j * 32;
        for (int i = tid; i < 32 * 16; i += 256) {
            int r = i >> 4, d4 = (i & 15) << 2;
            float4 kv = *(const float4*)(Kp + (size_t)(kbase + r) * HD + d4);
            Kt[d4+0][r] = kv.x; Kt[d4+1][r] = kv.y; Kt[d4+2][r] = kv.z; Kt[d4+3][r] = kv.w;
            float4 vv = *(const float4*)(Vp + (size_t)(kbase + r) * HD + d4);
            *(float4*)&Vs[r][d4] = vv;
        }
        __syncthreads();

        float s[4][2];
#pragma unroll
        for (int r = 0; r < 4; r++) { s[r][0] = 0.f; s[r][1] = 0.f; }
#pragma unroll 8
        for (int d = 0; d < 64; d++) {
            float qa[4], kb[2];
            *(float4*)qa = *(const float4*)&Qt[d][ty*4];
            *(float2*)kb = *(const float2*)&Kt[d][tx*2];
#pragma unroll
            for (int r = 0; r < 4; r++) { s[r][0] += qa[r]*kb[0]; s[r][1] += qa[r]*kb[1]; }
        }

        if (kbase >= PREFIX && kbase + 31 > qbase) {
#pragma unroll
            for (int r = 0; r < 4; r++) {
                int qq = qbase + ty * 4 + r;
#pragma unroll
                for (int c = 0; c < 2; c++)
                    if (kbase + tx * 2 + c > qq) s[r][c] = -1e30f;
            }
        }

#pragma unroll
        for (int r = 0; r < 4; r++) {
            float mx = fmaxf(s[r][0], s[r][1]);
#pragma unroll
            for (int o = 1; o < 16; o <<= 1) mx = fmaxf(mx, __shfl_xor_sync(0xffffffffu, mx, o));
            float mnew  = fmaxf(mi[r], mx);
            float alpha = __expf(mi[r] - mnew);
            float p0 = __expf(s[r][0] - mnew);
            float p1 = __expf(s[r][1] - mnew);
            float rs = p0 + p1;
#pragma unroll
            for (int o = 1; o < 16; o <<= 1) rs += __shfl_xor_sync(0xffffffffu, rs, o);
            li[r] = li[r] * alpha + rs;
            mi[r] = mnew;
#pragma unroll
            for (int c = 0; c < 4; c++) acc[r][c] *= alpha;
            Pt[tx*2 + 0][ty*4 + r] = p0;
            Pt[tx*2 + 1][ty*4 + r] = p1;
        }
        __syncthreads();

#pragma unroll 8
        for (int c2 = 0; c2 < 32; c2++) {
            float pa[4], vb[4];
            *(float4*)pa = *(const float4*)&Pt[c2][ty*4];
            *(float4*)vb = *(const float4*)&Vs[c2][tx*4];
#pragma unroll
            for (int r = 0; r < 4; r++)
#pragma unroll
                for (int c = 0; c < 4; c++) acc[r][c] += pa[r] * vb[c];
        }
    }

#pragma unroll
    for (int r = 0; r < 4; r++) {
        float inv = 1.0f / li[r];
        int srow = qbase + ty * 4 + r;
        float4 o = make_float4(acc[r][0]*inv, acc[r][1]*inv, acc[r][2]*inv, acc[r][3]*inv);
        *(float4*)&g_O[((size_t)(b*SEQ + srow))*DIM + h*HD + tx*4] = o;
    }
}

// ---------------------------------------------------------------------------
extern "C" void kernel_launch(void* const* d_in, const int* in_sizes, int n_in,
                              void* d_out, int out_size)
{
    const float* x      = (const float*)d_in[0];
    const float* qkv_w  = (const float*)d_in[1];
    const float* proj_w = (const float*)d_in[2];
    const float* proj_b = (const float*)d_in[3];
    float*       out    = (float*)d_out;

    // device addresses of __device__ globals (host symbol is a shadow!)
    void *px3, *pw3, *po3, *ppw3, *pgO;
    cudaGetSymbolAddress(&px3,  g_x3);
    cudaGetSymbolAddress(&pw3,  g_w3);
    cudaGetSymbolAddress(&po3,  g_o3);
    cudaGetSymbolAddress(&ppw3, g_pw3);
    cudaGetSymbolAddress(&pgO,  g_O);

    // split-3 conversions
    split3_kernel<0><<<(MROWS*DIM/4 + 255)/256, 256>>>(x,     (__nv_bfloat16*)px3,  MROWS*DIM/4);
    split3_kernel<1><<<(3*DIM*DIM/4 + 255)/256, 256>>>(qkv_w, (__nv_bfloat16*)pw3,  3*DIM*DIM/4);
    split3_kernel<1><<<(DIM*DIM/4   + 255)/256, 256>>>(proj_w,(__nv_bfloat16*)ppw3, DIM*DIM/4);

    // 1) QKV projection on tensor cores (HMMA): M=4096, N=3072, K'=3072
    mma_gemm<0><<<dim3(3*DIM/128, MROWS/128), 256>>>(
        (const __nv_bfloat16*)px3, (const __nv_bfloat16*)pw3, nullptr, nullptr);

    // 2) flash attention (fp32)
    attn_kernel<<<dim3(SEQ/64, BS*NH), 256>>>();

    // 3) split attention output, then proj GEMM + bias: M=4096, N=1024, K'=3072
    split3_kernel<0><<<(MROWS*DIM/4 + 255)/256, 256>>>((const float*)pgO, (__nv_bfloat16*)po3, MROWS*DIM/4);
    mma_gemm<1><<<dim3(DIM/128, MROWS/128), 256>>>(
        (const __nv_bfloat16*)po3, (const __nv_bfloat16*)ppw3, proj_b, out);
}

// round 7
// speedup vs baseline: 2.0438x; 1.5704x over previous
#include <cuda_runtime.h>
#include <cuda_bf16.h>
#include <cstdint>

#define BS   2
#define SEQ  2048
#define DIM  1024
#define NH   16
#define HD   64
#define PREFIX 256
#define MROWS (BS*SEQ)
#define KT   (3*DIM)          // tripled K for bf16-split GEMM

// ------------------------- device scratch (no allocs) -----------------------
__device__ __nv_bfloat16 g_Qh[BS*NH*SEQ*HD];
__device__ __nv_bfloat16 g_Ql[BS*NH*SEQ*HD];
__device__ __nv_bfloat16 g_Kh[BS*NH*SEQ*HD];
__device__ __nv_bfloat16 g_Kl[BS*NH*SEQ*HD];
__device__ __nv_bfloat16 g_Vh[BS*NH*SEQ*HD];
__device__ __nv_bfloat16 g_Vl[BS*NH*SEQ*HD];
__device__ __nv_bfloat16 g_x3 [MROWS*KT];      // x split-3      (4096 x 3072)
__device__ __nv_bfloat16 g_w3 [3*DIM*KT];      // qkv_w split-3  (3072 x 3072)
__device__ __nv_bfloat16 g_o3 [MROWS*KT];      // attn out split (4096 x 3072)
__device__ __nv_bfloat16 g_pw3[DIM*KT];        // proj_w split-3 (1024 x 3072)

// ------------------------- portable PTX helpers (sm_80+) --------------------
__device__ __forceinline__ uint32_t smem_u32(const void* p) {
    uint32_t a;
    asm("{ .reg .u64 t; cvta.to.shared.u64 t, %1; cvt.u32.u64 %0, t; }" : "=r"(a) : "l"(p));
    return a;
}
__device__ __forceinline__ void cp16(uint32_t saddr, const void* g) {
    asm volatile("cp.async.cg.shared.global [%0], [%1], 16;" :: "r"(saddr), "l"(g));
}
#define CP_COMMIT()  asm volatile("cp.async.commit_group;" ::: "memory")
#define CP_WAIT(n)   asm volatile("cp.async.wait_group %0;" :: "n"(n) : "memory")

__device__ __forceinline__ void ldsm4(uint32_t* r, uint32_t addr) {
    asm volatile("ldmatrix.sync.aligned.m8n8.x4.shared.b16 {%0,%1,%2,%3}, [%4];"
                 : "=r"(r[0]), "=r"(r[1]), "=r"(r[2]), "=r"(r[3]) : "r"(addr));
}
__device__ __forceinline__ void ldsm4t(uint32_t* r, uint32_t addr) {
    asm volatile("ldmatrix.sync.aligned.m8n8.x4.trans.shared.b16 {%0,%1,%2,%3}, [%4];"
                 : "=r"(r[0]), "=r"(r[1]), "=r"(r[2]), "=r"(r[3]) : "r"(addr));
}
__device__ __forceinline__ void mma16816(float* c, const uint32_t* a, uint32_t b0, uint32_t b1) {
    asm volatile("mma.sync.aligned.m16n8k16.row.col.f32.bf16.bf16.f32 "
                 "{%0,%1,%2,%3}, {%4,%5,%6,%7}, {%8,%9}, {%0,%1,%2,%3};"
                 : "+f"(c[0]), "+f"(c[1]), "+f"(c[2]), "+f"(c[3])
                 : "r"(a[0]), "r"(a[1]), "r"(a[2]), "r"(a[3]), "r"(b0), "r"(b1));
}
__device__ __forceinline__ uint32_t pk2(__nv_bfloat16 lo, __nv_bfloat16 hi) {
    __nv_bfloat162 t; t.x = lo; t.y = hi;
    return *(uint32_t*)&t;
}

// ---------------------------------------------------------------------------
// split-3 conversion: fp32 -> bf16 triplets.
// MODE 0 (A side): [hi, lo, hi]   MODE 1 (B side): [hi, hi, lo]
// ---------------------------------------------------------------------------
template<int MODE>
__global__ __launch_bounds__(256) void split3_kernel(const float* __restrict__ src,
                                                     __nv_bfloat16* __restrict__ dst,
                                                     int n4)
{
    int i = blockIdx.x * blockDim.x + threadIdx.x;
    if (i >= n4) return;
    float4 v = ((const float4*)src)[i];
    float xs[4] = {v.x, v.y, v.z, v.w};
    __nv_bfloat16 t[12];
#pragma unroll
    for (int j = 0; j < 4; j++) {
        __nv_bfloat16 hi = __float2bfloat16(xs[j]);
        __nv_bfloat16 lo = __float2bfloat16(xs[j] - __bfloat162float(hi));
        t[3*j+0] = hi;
        t[3*j+1] = (MODE == 0) ? lo : hi;
        t[3*j+2] = (MODE == 0) ? hi : lo;
    }
    uint2* dp = (uint2*)(dst + (size_t)i * 12);
    const uint2* tp = (const uint2*)t;
    dp[0] = tp[0]; dp[1] = tp[1]; dp[2] = tp[2];
}

// ---------------------------------------------------------------------------
// HMMA bf16 GEMM (known-good): C(128x128/CTA) = A3(M,KT) . B3(N,KT)^T.
// EPI 0: write Q/K/V as bf16 hi/lo pairs (Q * 0.125)   EPI 1: out = C + bias
// ---------------------------------------------------------------------------
template<int EPI>
__global__ __launch_bounds__(256) void mma_gemm(const __nv_bfloat16* __restrict__ A3,
                                                const __nv_bfloat16* __restrict__ B3,
                                                const float* __restrict__ bias,
                                                float* __restrict__ Cout)
{
    __shared__ __align__(16) __nv_bfloat16 sA[2][128*40];   // 80B row stride
    __shared__ __align__(16) __nv_bfloat16 sB[2][128*40];

    const int tid  = threadIdx.x;
    const int wid  = tid >> 5, lane = tid & 31;
    const int wm   = wid & 1,  wn   = wid >> 1;      // 2x4 warp grid
    const int bn   = blockIdx.x, bm = blockIdx.y;
    const int NCH  = KT / 32;                        // 96 chunks

    const char* Ab = (const char*)(A3 + (size_t)bm * 128 * KT);
    const char* Bb = (const char*)(B3 + (size_t)bn * 128 * KT);

    const uint32_t sA0 = smem_u32(&sA[0][0]);
    const uint32_t sB0 = smem_u32(&sB[0][0]);
    const uint32_t BUFB = 128 * 40 * 2;

    float acc[4][4][4];
#pragma unroll
    for (int i = 0; i < 4; i++)
#pragma unroll
        for (int j = 0; j < 4; j++)
#pragma unroll
            for (int k = 0; k < 4; k++) acc[i][j][k] = 0.f;

#define LOAD_TILE(c, buf)                                                          \
    {                                                                              \
        int koff = (c) * 64;                                                       \
        _Pragma("unroll")                                                          \
        for (int i = 0; i < 2; i++) {                                              \
            int idx = tid + i * 256;                                               \
            int row = idx >> 2, seg = idx & 3;                                     \
            uint32_t so = (uint32_t)(row * 80 + seg * 16 + (buf) * BUFB);          \
            cp16(sA0 + so, Ab + (size_t)row * (KT*2) + koff + seg * 16);           \
            cp16(sB0 + so, Bb + (size_t)row * (KT*2) + koff + seg * 16);           \
        }                                                                          \
    }

    LOAD_TILE(0, 0);
    CP_COMMIT();

    const int lrow = lane & 15;
    const int lcol = (lane >> 4) * 16;

    for (int c = 0; c < NCH; c++) {
        if (c + 1 < NCH) {
            LOAD_TILE(c + 1, (c + 1) & 1);
            CP_COMMIT();
            CP_WAIT(1);
        } else {
            CP_WAIT(0);
        }
        __syncthreads();

        uint32_t abase = sA0 + (c & 1) * BUFB;
        uint32_t bbase = sB0 + (c & 1) * BUFB;
#pragma unroll
        for (int kg = 0; kg < 2; kg++) {
            uint32_t a[4][4], b[2][4];
#pragma unroll
            for (int mt = 0; mt < 4; mt++)
                ldsm4(a[mt], abase + (uint32_t)((wm*64 + mt*16 + lrow) * 80 + kg*32 + lcol));
#pragma unroll
            for (int p = 0; p < 2; p++)
                ldsm4(b[p], bbase + (uint32_t)((wn*32 + p*16 + lrow) * 80 + kg*32 + lcol));
#pragma unroll
            for (int mt = 0; mt < 4; mt++)
#pragma unroll
                for (int nt = 0; nt < 4; nt++) {
                    int p = nt >> 1, q = nt & 1;
                    mma16816(acc[mt][nt], a[mt], b[p][q], b[p][q + 2]);
                }
        }
        __syncthreads();
    }

#pragma unroll
    for (int mt = 0; mt < 4; mt++) {
#pragma unroll
        for (int nt = 0; nt < 4; nt++) {
            int m0 = bm * 128 + wm * 64 + mt * 16 + (lane >> 2);
            int n0 = bn * 128 + wn * 32 + nt * 8 + 2 * (lane & 3);
            float c0 = acc[mt][nt][0], c1 = acc[mt][nt][1];
            float c2 = acc[mt][nt][2], c3 = acc[mt][nt][3];
            if (EPI == 0) {
                int part = n0 >> 10;
                __nv_bfloat16 *dh = (part == 0) ? g_Qh : (part == 1) ? g_Kh : g_Vh;
                __nv_bfloat16 *dl = (part == 0) ? g_Ql : (part == 1) ? g_Kl : g_Vl;
                float scl = (part == 0) ? 0.125f : 1.0f;
                int head = (n0 & 1023) >> 6, d = n0 & 63;
#pragma unroll
                for (int rr = 0; rr < 2; rr++) {
                    int m = m0 + rr * 8;
                    int bi = m >> 11, s = m & (SEQ - 1);
                    float v0 = (rr ? c2 : c0) * scl, v1 = (rr ? c3 : c1) * scl;
                    __nv_bfloat16 h0 = __float2bfloat16(v0);
                    __nv_bfloat16 l0 = __float2bfloat16(v0 - __bfloat162float(h0));
                    __nv_bfloat16 h1 = __float2bfloat16(v1);
                    __nv_bfloat16 l1 = __float2bfloat16(v1 - __bfloat162float(h1));
                    size_t idx = (((size_t)(bi*NH + head))*SEQ + s)*HD + d;
                    *(uint32_t*)&dh[idx] = pk2(h0, h1);
                    *(uint32_t*)&dl[idx] = pk2(l0, l1);
                }
            } else {
                float2 bv = *(const float2*)&bias[n0];
                *(float2*)&Cout[(size_t)m0 * DIM + n0]       = make_float2(c0 + bv.x, c1 + bv.y);
                *(float2*)&Cout[(size_t)(m0 + 8) * DIM + n0] = make_float2(c2 + bv.x, c3 + bv.y);
            }
        }
    }
}

// ---------------------------------------------------------------------------
// HMMA flash attention. CTA = 64 queries x one (b,h), 4 warps (128 threads).
// Warp w owns query rows w*16..w*16+15. 32-key chunks.
// QK^T: 3 passes (QhKh + QlKh + QhKl). PV: 3 passes (PhVh + PlVh + PhVl),
// P hi/lo built in registers from fp32 softmax probs (FA2 fragment repack).
// Output written directly as split-3 triplets into g_o3 for the proj GEMM.
// Mask: allowed(q,k) = (k <= q) || (k < 256); Q pre-scaled by 1/8.
// ---------------------------------------------------------------------------
__global__ __launch_bounds__(128) void attn_mma()
{
    __shared__ __align__(16) __nv_bfloat16 sQh[64*72];   // 144B row stride
    __shared__ __align__(16) __nv_bfloat16 sQl[64*72];
    __shared__ __align__(16) __nv_bfloat16 sKh[32*72];
    __shared__ __align__(16) __nv_bfloat16 sKl[32*72];
    __shared__ __align__(16) __nv_bfloat16 sVh[32*72];
    __shared__ __align__(16) __nv_bfloat16 sVl[32*72];

    const int qi  = blockIdx.x;            // 0..31
    const int bh  = blockIdx.y;            // 0..31
    const int b   = bh >> 4, h = bh & 15;
    const int tid = threadIdx.x, w = tid >> 5, lane = tid & 31;
    const int qbase = qi * 64;

    const size_t base = (size_t)bh * SEQ * HD;
    const uint32_t qh0 = smem_u32(sQh), ql0 = smem_u32(sQl);
    const uint32_t kh0 = smem_u32(sKh), kl0 = smem_u32(sKl);
    const uint32_t vh0 = smem_u32(sVh), vl0 = smem_u32(sVl);

    // load Q tile (64 rows x 64 bf16 = 8 segs of 16B per row)
    for (int i = tid; i < 512; i += 128) {
        int r = i >> 3, seg = i & 7;
        const char* gq = (const char*)(g_Qh + base + (size_t)(qbase + r) * HD);
        const char* gl = (const char*)(g_Ql + base + (size_t)(qbase + r) * HD);
        *(uint4*)((char*)sQh + r * 144 + seg * 16) = *(const uint4*)(gq + seg * 16);
        *(uint4*)((char*)sQl + r * 144 + seg * 16) = *(const uint4*)(gl + seg * 16);
    }

    float o[8][4];
#pragma unroll
    for (int i = 0; i < 8; i++)
#pragma unroll
        for (int j = 0; j < 4; j++) o[i][j] = 0.f;
    float mi[2] = {-1e30f, -1e30f}, li[2] = {0.f, 0.f};

    const int lrow  = lane & 15;
    const int lcolB = (lane >> 4) * 16;
    const int nch   = (qi < 4) ? 8 : 2 * (qi + 1);

    for (int ch = 0; ch < nch; ch++) {
        __syncthreads();                 // prev PV done before overwriting K/V
        const int kbase = ch * 32;
        for (int i = tid; i < 256; i += 128) {
            int r = i >> 3, seg = i & 7;
            size_t gidx = base + (size_t)(kbase + r) * HD;
            *(uint4*)((char*)sKh + r*144 + seg*16) = *(const uint4*)((const char*)(g_Kh + gidx) + seg*16);
            *(uint4*)((char*)sKl + r*144 + seg*16) = *(const uint4*)((const char*)(g_Kl + gidx) + seg*16);
            *(uint4*)((char*)sVh + r*144 + seg*16) = *(const uint4*)((const char*)(g_Vh + gidx) + seg*16);
            *(uint4*)((char*)sVl + r*144 + seg*16) = *(const uint4*)((const char*)(g_Vl + gidx) + seg*16);
        }
        __syncthreads();

        // ---- S = Q K^T (3 split passes), 4 n-tiles of 8 keys ----
        float s[4][4];
#pragma unroll
        for (int nt = 0; nt < 4; nt++)
#pragma unroll
            for (int j = 0; j < 4; j++) s[nt][j] = 0.f;

#pragma unroll
        for (int kg = 0; kg < 4; kg++) {
            uint32_t aH[4], aL[4], bH[2][4], bL[2][4];
            ldsm4(aH, qh0 + (uint32_t)((w*16 + lrow) * 144 + kg*32 + lcolB));
            ldsm4(aL, ql0 + (uint32_t)((w*16 + lrow) * 144 + kg*32 + lcolB));
#pragma unroll
            for (int p = 0; p < 2; p++) {
                ldsm4(bH[p], kh0 + (uint32_t)((p*16 + lrow) * 144 + kg*32 + lcolB));
                ldsm4(bL[p], kl0 + (uint32_t)((p*16 + lrow) * 144 + kg*32 + lcolB));
            }
#pragma unroll
            for (int nt = 0; nt < 4; nt++) {
                int p = nt >> 1, q = nt & 1;
                mma16816(s[nt], aH, bH[p][q], bH[p][q+2]);
                mma16816(s[nt], aL, bH[p][q], bH[p][q+2]);
                mma16816(s[nt], aH, bL[p][q], bL[p][q+2]);
            }
        }

        // ---- causal mask (only near-diagonal chunks outside prefix) ----
        if (kbase >= PREFIX && kbase + 31 > qbase) {
            int q0 = qbase + w*16 + (lane >> 2);
#pragma unroll
            for (int nt = 0; nt < 4; nt++) {
                int k0 = kbase + nt*8 + 2*(lane & 3);
                if (k0     > q0)     s[nt][0] = -1e30f;
                if (k0 + 1 > q0)     s[nt][1] = -1e30f;
                if (k0     > q0 + 8) s[nt][2] = -1e30f;
                if (k0 + 1 > q0 + 8) s[nt][3] = -1e30f;
            }
        }

        // ---- online softmax (rows r and r+8), quad shfl reductions ----
#pragma unroll
        for (int rr = 0; rr < 2; rr++) {
            float mx = -1e30f;
#pragma unroll
            for (int nt = 0; nt < 4; nt++)
                mx = fmaxf(mx, fmaxf(s[nt][2*rr], s[nt][2*rr+1]));
            mx = fmaxf(mx, __shfl_xor_sync(0xffffffffu, mx, 1));
            mx = fmaxf(mx, __shfl_xor_sync(0xffffffffu, mx, 2));
            float mnew  = fmaxf(mi[rr], mx);
            float alpha = __expf(mi[rr] - mnew);
            float rs = 0.f;
#pragma unroll
            for (int nt = 0; nt < 4; nt++) {
                float p0 = __expf(s[nt][2*rr]   - mnew);
                float p1 = __expf(s[nt][2*rr+1] - mnew);
                s[nt][2*rr] = p0; s[nt][2*rr+1] = p1;
                rs += p0 + p1;
            }
            rs += __shfl_xor_sync(0xffffffffu, rs, 1);
            rs += __shfl_xor_sync(0xffffffffu, rs, 2);
            li[rr] = li[rr] * alpha + rs;
            mi[rr] = mnew;
#pragma unroll
            for (int dn = 0; dn < 8; dn++) {
                o[dn][2*rr] *= alpha; o[dn][2*rr+1] *= alpha;
            }
        }

        // ---- O += P V (3 split passes); P frags built in registers ----
#pragma unroll
        for (int kt = 0; kt < 2; kt++) {
            uint32_t pH[4], pL[4];
#pragma unroll
            for (int half = 0; half < 2; half++) {
                float* sv = s[2*kt + half];
                __nv_bfloat16 h0 = __float2bfloat16(sv[0]);
                __nv_bfloat16 h1 = __float2bfloat16(sv[1]);
                __nv_bfloat16 h2 = __float2bfloat16(sv[2]);
                __nv_bfloat16 h3 = __float2bfloat16(sv[3]);
                __nv_bfloat16 l0 = __float2bfloat16(sv[0] - __bfloat162float(h0));
                __nv_bfloat16 l1 = __float2bfloat16(sv[1] - __bfloat162float(h1));
                __nv_bfloat16 l2 = __float2bfloat16(sv[2] - __bfloat162float(h2));
                __nv_bfloat16 l3 = __float2bfloat16(sv[3] - __bfloat162float(h3));
                pH[half*2+0] = pk2(h0, h1); pH[half*2+1] = pk2(h2, h3);
                pL[half*2+0] = pk2(l0, l1); pL[half*2+1] = pk2(l2, l3);
            }
#pragma unroll
            for (int p4 = 0; p4 < 4; p4++) {
                uint32_t vH[4], vL[4];
                ldsm4t(vH, vh0 + (uint32_t)((kt*16 + lrow) * 144 + p4*32 + lcolB));
                ldsm4t(vL, vl0 + (uint32_t)((kt*16 + lrow) * 144 + p4*32 + lcolB));
                mma16816(o[2*p4],   pH, vH[0], vH[1]);
                mma16816(o[2*p4],   pL, vH[0], vH[1]);
                mma16816(o[2*p4],   pH, vL[0], vL[1]);
                mma16816(o[2*p4+1], pH, vH[2], vH[3]);
                mma16816(o[2*p4+1], pL, vH[2], vH[3]);
                mma16816(o[2*p4+1], pH, vL[2], vL[3]);
            }
        }
    }

    // ---- epilogue: normalize, split-3, write g_o3 triplets [hi,lo,hi] ----
#pragma unroll
    for (int dn = 0; dn < 8; dn++) {
        int d0 = dn*8 + 2*(lane & 3);
#pragma unroll
        for (int rr = 0; rr < 2; rr++) {
            int row = qbase + w*16 + (lane >> 2) + rr*8;
            float inv = 1.0f / li[rr];
            float v0 = o[dn][2*rr]   * inv;
            float v1 = o[dn][2*rr+1] * inv;
            __nv_bfloat16 h0 = __float2bfloat16(v0);
            __nv_bfloat16 l0 = __float2bfloat16(v0 - __bfloat162float(h0));
            __nv_bfloat16 h1 = __float2bfloat16(v1);
            __nv_bfloat16 l1 = __float2bfloat16(v1 - __bfloat162float(h1));
            size_t off = (size_t)(b*SEQ + row) * KT + (size_t)3 * (h*HD + d0);
            *(uint32_t*)&g_o3[off]     = pk2(h0, l0);
            *(uint32_t*)&g_o3[off + 2] = pk2(h0, h1);
            *(uint32_t*)&g_o3[off + 4] = pk2(l1, h1);
        }
    }
}

// ---------------------------------------------------------------------------
extern "C" void kernel_launch(void* const* d_in, const int* in_sizes, int n_in,
                              void* d_out, int out_size)
{
    const float* x      = (const float*)d_in[0];
    const float* qkv_w  = (const float*)d_in[1];
    const float* proj_w = (const float*)d_in[2];
    const float* proj_b = (const float*)d_in[3];
    float*       out    = (float*)d_out;

    // device addresses of __device__ globals (host symbol is a shadow!)
    void *px3, *pw3, *po3, *ppw3;
    cudaGetSymbolAddress(&px3,  g_x3);
    cudaGetSymbolAddress(&pw3,  g_w3);
    cudaGetSymbolAddress(&po3,  g_o3);
    cudaGetSymbolAddress(&ppw3, g_pw3);

    // split-3 conversions (weights + input)
    split3_kernel<0><<<(MROWS*DIM/4 + 255)/256, 256>>>(x,     (__nv_bfloat16*)px3,  MROWS*DIM/4);
    split3_kernel<1><<<(3*DIM*DIM/4 + 255)/256, 256>>>(qkv_w, (__nv_bfloat16*)pw3,  3*DIM*DIM/4);
    split3_kernel<1><<<(DIM*DIM/4   + 255)/256, 256>>>(proj_w,(__nv_bfloat16*)ppw3, DIM*DIM/4);

    // 1) QKV projection (HMMA), epilogue emits bf16 hi/lo Q/K/V
    mma_gemm<0><<<dim3(3*DIM/128, MROWS/128), 256>>>(
        (const __nv_bfloat16*)px3, (const __nv_bfloat16*)pw3, nullptr, nullptr);

    // 2) flash attention (HMMA, split-3), epilogue emits split-3 O
    attn_mma<<<dim3(SEQ/64, BS*NH), 128>>>();

    // 3) proj GEMM + bias (HMMA)
    mma_gemm<1><<<dim3(DIM/128, MROWS/128), 256>>>(
        (const __nv_bfloat16*)po3, (const __nv_bfloat16*)ppw3, proj_b, out);
}

// round 8
// speedup vs baseline: 2.5904x; 1.2674x over previous
#include <cuda_runtime.h>
#include <cuda_bf16.h>
#include <cstdint>

#define BS   2
#define SEQ  2048
#define DIM  1024
#define NH   16
#define HD   64
#define PREFIX 256
#define MROWS (BS*SEQ)
#define KT   (3*DIM)          // tripled K for bf16-split GEMM

// ------------------------- device scratch (no allocs) -----------------------
__device__ __nv_bfloat16 g_Qh[BS*NH*SEQ*HD];
__device__ __nv_bfloat16 g_Ql[BS*NH*SEQ*HD];
__device__ __nv_bfloat16 g_Kh[BS*NH*SEQ*HD];
__device__ __nv_bfloat16 g_Kl[BS*NH*SEQ*HD];
__device__ __nv_bfloat16 g_Vh[BS*NH*SEQ*HD];
__device__ __nv_bfloat16 g_Vl[BS*NH*SEQ*HD];
__device__ __nv_bfloat16 g_x3 [MROWS*KT];      // x split-3      (4096 x 3072)
__device__ __nv_bfloat16 g_w3 [3*DIM*KT];      // qkv_w split-3  (3072 x 3072)
__device__ __nv_bfloat16 g_o3 [MROWS*KT];      // attn out split (4096 x 3072)
__device__ __nv_bfloat16 g_pw3[DIM*KT];        // proj_w split-3 (1024 x 3072)

// ------------------------- portable PTX helpers (sm_80+) --------------------
__device__ __forceinline__ uint32_t smem_u32(const void* p) {
    uint32_t a;
    asm("{ .reg .u64 t; cvta.to.shared.u64 t, %1; cvt.u32.u64 %0, t; }" : "=r"(a) : "l"(p));
    return a;
}
__device__ __forceinline__ void cp16(uint32_t saddr, const void* g) {
    asm volatile("cp.async.cg.shared.global [%0], [%1], 16;" :: "r"(saddr), "l"(g));
}
#define CP_COMMIT()  asm volatile("cp.async.commit_group;" ::: "memory")
#define CP_WAIT(n)   asm volatile("cp.async.wait_group %0;" :: "n"(n) : "memory")

__device__ __forceinline__ void ldsm4(uint32_t* r, uint32_t addr) {
    asm volatile("ldmatrix.sync.aligned.m8n8.x4.shared.b16 {%0,%1,%2,%3}, [%4];"
                 : "=r"(r[0]), "=r"(r[1]), "=r"(r[2]), "=r"(r[3]) : "r"(addr));
}
__device__ __forceinline__ void ldsm4t(uint32_t* r, uint32_t addr) {
    asm volatile("ldmatrix.sync.aligned.m8n8.x4.trans.shared.b16 {%0,%1,%2,%3}, [%4];"
                 : "=r"(r[0]), "=r"(r[1]), "=r"(r[2]), "=r"(r[3]) : "r"(addr));
}
__device__ __forceinline__ void mma16816(float* c, const uint32_t* a, uint32_t b0, uint32_t b1) {
    asm volatile("mma.sync.aligned.m16n8k16.row.col.f32.bf16.bf16.f32 "
                 "{%0,%1,%2,%3}, {%4,%5,%6,%7}, {%8,%9}, {%0,%1,%2,%3};"
                 : "+f"(c[0]), "+f"(c[1]), "+f"(c[2]), "+f"(c[3])
                 : "r"(a[0]), "r"(a[1]), "r"(a[2]), "r"(a[3]), "r"(b0), "r"(b1));
}
__device__ __forceinline__ uint32_t pk2(__nv_bfloat16 lo, __nv_bfloat16 hi) {
    __nv_bfloat162 t; t.x = lo; t.y = hi;
    return *(uint32_t*)&t;
}

// ---------------------------------------------------------------------------
// split-3 conversion: fp32 -> bf16 triplets.
// MODE 0 (A side): [hi, lo, hi]   MODE 1 (B side): [hi, hi, lo]
// ---------------------------------------------------------------------------
template<int MODE>
__global__ __launch_bounds__(256) void split3_kernel(const float* __restrict__ src,
                                                     __nv_bfloat16* __restrict__ dst,
                                                     int n4)
{
    int i = blockIdx.x * blockDim.x + threadIdx.x;
    if (i >= n4) return;
    float4 v = ((const float4*)src)[i];
    float xs[4] = {v.x, v.y, v.z, v.w};
    __nv_bfloat16 t[12];
#pragma unroll
    for (int j = 0; j < 4; j++) {
        __nv_bfloat16 hi = __float2bfloat16(xs[j]);
        __nv_bfloat16 lo = __float2bfloat16(xs[j] - __bfloat162float(hi));
        t[3*j+0] = hi;
        t[3*j+1] = (MODE == 0) ? lo : hi;
        t[3*j+2] = (MODE == 0) ? hi : lo;
    }
    uint2* dp = (uint2*)(dst + (size_t)i * 12);
    const uint2* tp = (const uint2*)t;
    dp[0] = tp[0]; dp[1] = tp[1]; dp[2] = tp[2];
}

// ---------------------------------------------------------------------------
// HMMA bf16 GEMM: C(128x128/CTA) = A3(M,KT) . B3(N,KT)^T, fp32 accum.
// 3-stage cp.async pipeline, 64B rows with XOR swizzle (seg ^= (row>>1)&3):
// 48KB static smem exactly, loads issued 2 chunks ahead, ONE sync per chunk.
// EPI 0: write Q/K/V as bf16 hi/lo pairs (Q * 0.125)   EPI 1: out = C + bias
// ---------------------------------------------------------------------------
template<int EPI>
__global__ __launch_bounds__(256, 2) void mma_gemm(const __nv_bfloat16* __restrict__ A3,
                                                   const __nv_bfloat16* __restrict__ B3,
                                                   const float* __restrict__ bias,
                                                   float* __restrict__ Cout)
{
    __shared__ __align__(16) __nv_bfloat16 sA[3][128*32];   // 64B rows, swizzled
    __shared__ __align__(16) __nv_bfloat16 sB[3][128*32];

    const int tid  = threadIdx.x;
    const int wid  = tid >> 5, lane = tid & 31;
    const int wm   = wid & 1,  wn   = wid >> 1;      // 2x4 warp grid
    const int bn   = blockIdx.x, bm = blockIdx.y;
    const int NCH  = KT / 32;                        // 96 chunks
    const uint32_t STB = 128 * 64;                   // stage bytes = 8192

    const char* Ab = (const char*)(A3 + (size_t)bm * 128 * KT);
    const char* Bb = (const char*)(B3 + (size_t)bn * 128 * KT);

    const uint32_t sA0 = smem_u32(&sA[0][0]);
    const uint32_t sB0 = smem_u32(&sB[0][0]);

    float acc[4][4][4];
#pragma unroll
    for (int i = 0; i < 4; i++)
#pragma unroll
        for (int j = 0; j < 4; j++)
#pragma unroll
            for (int k = 0; k < 4; k++) acc[i][j][k] = 0.f;

    // per chunk: each thread moves 2 x 16B per operand (idx = tid + i*256)
#define LOAD_TILE(c, st)                                                           \
    {                                                                              \
        int koff = (c) * 64;                                                       \
        _Pragma("unroll")                                                          \
        for (int i = 0; i < 2; i++) {                                              \
            int idx = tid + i * 256;                                               \
            int row = idx >> 2, seg = idx & 3;                                     \
            int pseg = seg ^ ((row >> 1) & 3);                                     \
            uint32_t so = (uint32_t)((st) * STB + row * 64 + pseg * 16);           \
            cp16(sA0 + so, Ab + (size_t)row * (KT*2) + koff + seg * 16);           \
            cp16(sB0 + so, Bb + (size_t)row * (KT*2) + koff + seg * 16);           \
        }                                                                          \
    }

    LOAD_TILE(0, 0); CP_COMMIT();
    LOAD_TILE(1, 1); CP_COMMIT();

    const int lrow = lane & 15;
    const int lhalf = lane >> 4;                     // 0/1 -> +16B column

    int st = 0;                                      // stage of chunk c
    for (int c = 0; c < NCH; c++) {
        CP_WAIT(1);                                  // stage of chunk c complete
        __syncthreads();                             // everyone done with c-1 too

        // prefetch chunk c+2 into the stage compute(c-1) just released
        if (c + 2 < NCH) {
            int st2 = (st + 2 >= 3) ? st - 1 : st + 2;
            LOAD_TILE(c + 2, st2);
        }
        CP_COMMIT();

        uint32_t abase = sA0 + st * STB;
        uint32_t bbase = sB0 + st * STB;
#pragma unroll
        for (int kg = 0; kg < 2; kg++) {
            uint32_t a[4][4], b[2][4];
            int lseg = kg * 2 + lhalf;
#pragma unroll
            for (int mt = 0; mt < 4; mt++) {
                int row = wm*64 + mt*16 + lrow;
                ldsm4(a[mt], abase + (uint32_t)(row * 64 + (lseg ^ ((row >> 1) & 3)) * 16));
            }
#pragma unroll
            for (int p = 0; p < 2; p++) {
                int row = wn*32 + p*16 + lrow;
                ldsm4(b[p], bbase + (uint32_t)(row * 64 + (lseg ^ ((row >> 1) & 3)) * 16));
            }
#pragma unroll
            for (int mt = 0; mt < 4; mt++)
#pragma unroll
                for (int nt = 0; nt < 4; nt++) {
                    int p = nt >> 1, q = nt & 1;
                    mma16816(acc[mt][nt], a[mt], b[p][q], b[p][q + 2]);
                }
        }
        st = (st + 1 >= 3) ? 0 : st + 1;
    }

#pragma unroll
    for (int mt = 0; mt < 4; mt++) {
#pragma unroll
        for (int nt = 0; nt < 4; nt++) {
            int m0 = bm * 128 + wm * 64 + mt * 16 + (lane >> 2);
            int n0 = bn * 128 + wn * 32 + nt * 8 + 2 * (lane & 3);
            float c0 = acc[mt][nt][0], c1 = acc[mt][nt][1];
            float c2 = acc[mt][nt][2], c3 = acc[mt][nt][3];
            if (EPI == 0) {
                int part = n0 >> 10;
                __nv_bfloat16 *dh = (part == 0) ? g_Qh : (part == 1) ? g_Kh : g_Vh;
                __nv_bfloat16 *dl = (part == 0) ? g_Ql : (part == 1) ? g_Kl : g_Vl;
                float scl = (part == 0) ? 0.125f : 1.0f;
                int head = (n0 & 1023) >> 6, d = n0 & 63;
#pragma unroll
                for (int rr = 0; rr < 2; rr++) {
                    int m = m0 + rr * 8;
                    int bi = m >> 11, s = m & (SEQ - 1);
                    float v0 = (rr ? c2 : c0) * scl, v1 = (rr ? c3 : c1) * scl;
                    __nv_bfloat16 h0 = __float2bfloat16(v0);
                    __nv_bfloat16 l0 = __float2bfloat16(v0 - __bfloat162float(h0));
                    __nv_bfloat16 h1 = __float2bfloat16(v1);
                    __nv_bfloat16 l1 = __float2bfloat16(v1 - __bfloat162float(h1));
                    size_t idx = (((size_t)(bi*NH + head))*SEQ + s)*HD + d;
                    *(uint32_t*)&dh[idx] = pk2(h0, h1);
                    *(uint32_t*)&dl[idx] = pk2(l0, l1);
                }
            } else {
                float2 bv = *(const float2*)&bias[n0];
                *(float2*)&Cout[(size_t)m0 * DIM + n0]       = make_float2(c0 + bv.x, c1 + bv.y);
                *(float2*)&Cout[(size_t)(m0 + 8) * DIM + n0] = make_float2(c2 + bv.x, c3 + bv.y);
            }
        }
    }
}

// ---------------------------------------------------------------------------
// HMMA flash attention (unchanged from passing round 7).
// ---------------------------------------------------------------------------
__global__ __launch_bounds__(128) void attn_mma()
{
    __shared__ __align__(16) __nv_bfloat16 sQh[64*72];   // 144B row stride
    __shared__ __align__(16) __nv_bfloat16 sQl[64*72];
    __shared__ __align__(16) __nv_bfloat16 sKh[32*72];
    __shared__ __align__(16) __nv_bfloat16 sKl[32*72];
    __shared__ __align__(16) __nv_bfloat16 sVh[32*72];
    __shared__ __align__(16) __nv_bfloat16 sVl[32*72];

    const int qi  = blockIdx.x;
    const int bh  = blockIdx.y;
    const int b   = bh >> 4, h = bh & 15;
    const int tid = threadIdx.x, w = tid >> 5, lane = tid & 31;
    const int qbase = qi * 64;

    const size_t base = (size_t)bh * SEQ * HD;
    const uint32_t qh0 = smem_u32(sQh), ql0 = smem_u32(sQl);
    const uint32_t kh0 = smem_u32(sKh), kl0 = smem_u32(sKl);
    const uint32_t vh0 = smem_u32(sVh), vl0 = smem_u32(sVl);

    for (int i = tid; i < 512; i += 128) {
        int r = i >> 3, seg = i & 7;
        const char* gq = (const char*)(g_Qh + base + (size_t)(qbase + r) * HD);
        const char* gl = (const char*)(g_Ql + base + (size_t)(qbase + r) * HD);
        *(uint4*)((char*)sQh + r * 144 + seg * 16) = *(const uint4*)(gq + seg * 16);
        *(uint4*)((char*)sQl + r * 144 + seg * 16) = *(const uint4*)(gl + seg * 16);
    }

    float o[8][4];
#pragma unroll
    for (int i = 0; i < 8; i++)
#pragma unroll
        for (int j = 0; j < 4; j++) o[i][j] = 0.f;
    float mi[2] = {-1e30f, -1e30f}, li[2] = {0.f, 0.f};

    const int lrow  = lane & 15;
    const int lcolB = (lane >> 4) * 16;
    const int nch   = (qi < 4) ? 8 : 2 * (qi + 1);

    for (int ch = 0; ch < nch; ch++) {
        __syncthreads();
        const int kbase = ch * 32;
        for (int i = tid; i < 256; i += 128) {
            int r = i >> 3, seg = i & 7;
            size_t gidx = base + (size_t)(kbase + r) * HD;
            *(uint4*)((char*)sKh + r*144 + seg*16) = *(const uint4*)((const char*)(g_Kh + gidx) + seg*16);
            *(uint4*)((char*)sKl + r*144 + seg*16) = *(const uint4*)((const char*)(g_Kl + gidx) + seg*16);
            *(uint4*)((char*)sVh + r*144 + seg*16) = *(const uint4*)((const char*)(g_Vh + gidx) + seg*16);
            *(uint4*)((char*)sVl + r*144 + seg*16) = *(const uint4*)((const char*)(g_Vl + gidx) + seg*16);
        }
        __syncthreads();

        float s[4][4];
#pragma unroll
        for (int nt = 0; nt < 4; nt++)
#pragma unroll
            for (int j = 0; j < 4; j++) s[nt][j] = 0.f;

#pragma unroll
        for (int kg = 0; kg < 4; kg++) {
            uint32_t aH[4], aL[4], bH[2][4], bL[2][4];
            ldsm4(aH, qh0 + (uint32_t)((w*16 + lrow) * 144 + kg*32 + lcolB));
            ldsm4(aL, ql0 + (uint32_t)((w*16 + lrow) * 144 + kg*32 + lcolB));
#pragma unroll
            for (int p = 0; p < 2; p++) {
                ldsm4(bH[p], kh0 + (uint32_t)((p*16 + lrow) * 144 + kg*32 + lcolB));
                ldsm4(bL[p], kl0 + (uint32_t)((p*16 + lrow) * 144 + kg*32 + lcolB));
            }
#pragma unroll
            for (int nt = 0; nt < 4; nt++) {
                int p = nt >> 1, q = nt & 1;
                mma16816(s[nt], aH, bH[p][q], bH[p][q+2]);
                mma16816(s[nt], aL, bH[p][q], bH[p][q+2]);
                mma16816(s[nt], aH, bL[p][q], bL[p][q+2]);
            }
        }

        if (kbase >= PREFIX && kbase + 31 > qbase) {
            int q0 = qbase + w*16 + (lane >> 2);
#pragma unroll
            for (int nt = 0; nt < 4; nt++) {
                int k0 = kbase + nt*8 + 2*(lane & 3);
                if (k0     > q0)     s[nt][0] = -1e30f;
                if (k0 + 1 > q0)     s[nt][1] = -1e30f;
                if (k0     > q0 + 8) s[nt][2] = -1e30f;
                if (k0 + 1 > q0 + 8) s[nt][3] = -1e30f;
            }
        }

#pragma unroll
        for (int rr = 0; rr < 2; rr++) {
            float mx = -1e30f;
#pragma unroll
            for (int nt = 0; nt < 4; nt++)
                mx = fmaxf(mx, fmaxf(s[nt][2*rr], s[nt][2*rr+1]));
            mx = fmaxf(mx, __shfl_xor_sync(0xffffffffu, mx, 1));
            mx = fmaxf(mx, __shfl_xor_sync(0xffffffffu, mx, 2));
            float mnew  = fmaxf(mi[rr], mx);
            float alpha = __expf(mi[rr] - mnew);
            float rs = 0.f;
#pragma unroll
            for (int nt = 0; nt < 4; nt++) {
                float p0 = __expf(s[nt][2*rr]   - mnew);
                float p1 = __expf(s[nt][2*rr+1] - mnew);
                s[nt][2*rr] = p0; s[nt][2*rr+1] = p1;
                rs += p0 + p1;
            }
            rs += __shfl_xor_sync(0xffffffffu, rs, 1);
            rs += __shfl_xor_sync(0xffffffffu, rs, 2);
            li[rr] = li[rr] * alpha + rs;
            mi[rr] = mnew;
#pragma unroll
            for (int dn = 0; dn < 8; dn++) {
                o[dn][2*rr] *= alpha; o[dn][2*rr+1] *= alpha;
            }
        }

#pragma unroll
        for (int kt = 0; kt < 2; kt++) {
            uint32_t pH[4], pL[4];
#pragma unroll
            for (int half = 0; half < 2; half++) {
                float* sv = s[2*kt + half];
                __nv_bfloat16 h0 = __float2bfloat16(sv[0]);
                __nv_bfloat16 h1 = __float2bfloat16(sv[1]);
                __nv_bfloat16 h2 = __float2bfloat16(sv[2]);
                __nv_bfloat16 h3 = __float2bfloat16(sv[3]);
                __nv_bfloat16 l0 = __float2bfloat16(sv[0] - __bfloat162float(h0));
                __nv_bfloat16 l1 = __float2bfloat16(sv[1] - __bfloat162float(h1));
                __nv_bfloat16 l2 = __float2bfloat16(sv[2] - __bfloat162float(h2));
                __nv_bfloat16 l3 = __float2bfloat16(sv[3] - __bfloat162float(h3));
                pH[half*2+0] = pk2(h0, h1); pH[half*2+1] = pk2(h2, h3);
                pL[half*2+0] = pk2(l0, l1); pL[half*2+1] = pk2(l2, l3);
            }
#pragma unroll
            for (int p4 = 0; p4 < 4; p4++) {
                uint32_t vH[4], vL[4];
                ldsm4t(vH, vh0 + (uint32_t)((kt*16 + lrow) * 144 + p4*32 + lcolB));
                ldsm4t(vL, vl0 + (uint32_t)((kt*16 + lrow) * 144 + p4*32 + lcolB));
                mma16816(o[2*p4],   pH, vH[0], vH[1]);
                mma16816(o[2*p4],   pL, vH[0], vH[1]);
                mma16816(o[2*p4],   pH, vL[0], vL[1]);
                mma16816(o[2*p4+1], pH, vH[2], vH[3]);
                mma16816(o[2*p4+1], pL, vH[2], vH[3]);
                mma16816(o[2*p4+1], pH, vL[2], vL[3]);
            }
        }
    }

#pragma unroll
    for (int dn = 0; dn < 8; dn++) {
        int d0 = dn*8 + 2*(lane & 3);
#pragma unroll
        for (int rr = 0; rr < 2; rr++) {
            int row = qbase + w*16 + (lane >> 2) + rr*8;
            float inv = 1.0f / li[rr];
            float v0 = o[dn][2*rr]   * inv;
            float v1 = o[dn][2*rr+1] * inv;
            __nv_bfloat16 h0 = __float2bfloat16(v0);
            __nv_bfloat16 l0 = __float2bfloat16(v0 - __bfloat162float(h0));
            __nv_bfloat16 h1 = __float2bfloat16(v1);
            __nv_bfloat16 l1 = __float2bfloat16(v1 - __bfloat162float(h1));
            size_t off = (size_t)(b*SEQ + row) * KT + (size_t)3 * (h*HD + d0);
            *(uint32_t*)&g_o3[off]     = pk2(h0, l0);
            *(uint32_t*)&g_o3[off + 2] = pk2(h0, h1);
            *(uint32_t*)&g_o3[off + 4] = pk2(l1, h1);
        }
    }
}

// ---------------------------------------------------------------------------
extern "C" void kernel_launch(void* const* d_in, const int* in_sizes, int n_in,
                              void* d_out, int out_size)
{
    const float* x      = (const float*)d_in[0];
    const float* qkv_w  = (const float*)d_in[1];
    const float* proj_w = (const float*)d_in[2];
    const float* proj_b = (const float*)d_in[3];
    float*       out    = (float*)d_out;

    void *px3, *pw3, *po3, *ppw3;
    cudaGetSymbolAddress(&px3,  g_x3);
    cudaGetSymbolAddress(&pw3,  g_w3);
    cudaGetSymbolAddress(&po3,  g_o3);
    cudaGetSymbolAddress(&ppw3, g_pw3);

    split3_kernel<0><<<(MROWS*DIM/4 + 255)/256, 256>>>(x,     (__nv_bfloat16*)px3,  MROWS*DIM/4);
    split3_kernel<1><<<(3*DIM*DIM/4 + 255)/256, 256>>>(qkv_w, (__nv_bfloat16*)pw3,  3*DIM*DIM/4);
    split3_kernel<1><<<(DIM*DIM/4   + 255)/256, 256>>>(proj_w,(__nv_bfloat16*)ppw3, DIM*DIM/4);

    mma_gemm<0><<<dim3(3*DIM/128, MROWS/128), 256>>>(
        (const __nv_bfloat16*)px3, (const __nv_bfloat16*)pw3, nullptr, nullptr);

    attn_mma<<<dim3(SEQ/64, BS*NH), 128>>>();

    mma_gemm<1><<<dim3(DIM/128, MROWS/128), 256>>>(
        (const __nv_bfloat16*)po3, (const __nv_bfloat16*)ppw3, proj_b, out);
}

// round 9
// speedup vs baseline: 2.6749x; 1.0327x over previous
#include <cuda_runtime.h>
#include <cuda_bf16.h>
#include <cstdint>

#define BS   2
#define SEQ  2048
#define DIM  1024
#define NH   16
#define HD   64
#define PREFIX 256
#define MROWS (BS*SEQ)
#define KT   (3*DIM)          // tripled K for bf16-split GEMM

// ------------------------- device scratch (no allocs) -----------------------
__device__ __nv_bfloat16 g_Qh[BS*NH*SEQ*HD];
__device__ __nv_bfloat16 g_Ql[BS*NH*SEQ*HD];
__device__ __nv_bfloat16 g_Kh[BS*NH*SEQ*HD];
__device__ __nv_bfloat16 g_Kl[BS*NH*SEQ*HD];
__device__ __nv_bfloat16 g_Vh[BS*NH*SEQ*HD];
__device__ __nv_bfloat16 g_Vl[BS*NH*SEQ*HD];
__device__ __nv_bfloat16 g_x3 [MROWS*KT];      // x split-3      (4096 x 3072)
__device__ __nv_bfloat16 g_w3 [3*DIM*KT];      // qkv_w split-3  (3072 x 3072)
__device__ __nv_bfloat16 g_o3 [MROWS*KT];      // attn out split (4096 x 3072)
__device__ __nv_bfloat16 g_pw3[DIM*KT];        // proj_w split-3 (1024 x 3072)

// ------------------------- portable PTX helpers (sm_80+) --------------------
__device__ __forceinline__ uint32_t smem_u32(const void* p) {
    uint32_t a;
    asm("{ .reg .u64 t; cvta.to.shared.u64 t, %1; cvt.u32.u64 %0, t; }" : "=r"(a) : "l"(p));
    return a;
}
__device__ __forceinline__ void cp16(uint32_t saddr, const void* g) {
    asm volatile("cp.async.cg.shared.global [%0], [%1], 16;" :: "r"(saddr), "l"(g));
}
#define CP_COMMIT()  asm volatile("cp.async.commit_group;" ::: "memory")
#define CP_WAIT(n)   asm volatile("cp.async.wait_group %0;" :: "n"(n) : "memory")

__device__ __forceinline__ void ldsm4(uint32_t* r, uint32_t addr) {
    asm volatile("ldmatrix.sync.aligned.m8n8.x4.shared.b16 {%0,%1,%2,%3}, [%4];"
                 : "=r"(r[0]), "=r"(r[1]), "=r"(r[2]), "=r"(r[3]) : "r"(addr));
}
__device__ __forceinline__ void ldsm4t(uint32_t* r, uint32_t addr) {
    asm volatile("ldmatrix.sync.aligned.m8n8.x4.trans.shared.b16 {%0,%1,%2,%3}, [%4];"
                 : "=r"(r[0]), "=r"(r[1]), "=r"(r[2]), "=r"(r[3]) : "r"(addr));
}
__device__ __forceinline__ void mma16816(float* c, const uint32_t* a, uint32_t b0, uint32_t b1) {
    asm volatile("mma.sync.aligned.m16n8k16.row.col.f32.bf16.bf16.f32 "
                 "{%0,%1,%2,%3}, {%4,%5,%6,%7}, {%8,%9}, {%0,%1,%2,%3};"
                 : "+f"(c[0]), "+f"(c[1]), "+f"(c[2]), "+f"(c[3])
                 : "r"(a[0]), "r"(a[1]), "r"(a[2]), "r"(a[3]), "r"(b0), "r"(b1));
}
__device__ __forceinline__ uint32_t pk2(__nv_bfloat16 lo, __nv_bfloat16 hi) {
    __nv_bfloat162 t; t.x = lo; t.y = hi;
    return *(uint32_t*)&t;
}

// ---------------------------------------------------------------------------
// split-3 conversion: fp32 -> bf16 triplets.
// MODE 0 (A side): [hi, lo, hi]   MODE 1 (B side): [hi, hi, lo]
// ---------------------------------------------------------------------------
template<int MODE>
__global__ __launch_bounds__(256) void split3_kernel(const float* __restrict__ src,
                                                     __nv_bfloat16* __restrict__ dst,
                                                     int n4)
{
    int i = blockIdx.x * blockDim.x + threadIdx.x;
    if (i >= n4) return;
    float4 v = ((const float4*)src)[i];
    float xs[4] = {v.x, v.y, v.z, v.w};
    __nv_bfloat16 t[12];
#pragma unroll
    for (int j = 0; j < 4; j++) {
        __nv_bfloat16 hi = __float2bfloat16(xs[j]);
        __nv_bfloat16 lo = __float2bfloat16(xs[j] - __bfloat162float(hi));
        t[3*j+0] = hi;
        t[3*j+1] = (MODE == 0) ? lo : hi;
        t[3*j+2] = (MODE == 0) ? hi : lo;
    }
    uint2* dp = (uint2*)(dst + (size_t)i * 12);
    const uint2* tp = (const uint2*)t;
    dp[0] = tp[0]; dp[1] = tp[1]; dp[2] = tp[2];
}

// ---------------------------------------------------------------------------
// HMMA bf16 GEMM (UNCHANGED from round 8 — known-good, 49% tensor).
// ---------------------------------------------------------------------------
template<int EPI>
__global__ __launch_bounds__(256, 2) void mma_gemm(const __nv_bfloat16* __restrict__ A3,
                                                   const __nv_bfloat16* __restrict__ B3,
                                                   const float* __restrict__ bias,
                                                   float* __restrict__ Cout)
{
    __shared__ __align__(16) __nv_bfloat16 sA[3][128*32];   // 64B rows, swizzled
    __shared__ __align__(16) __nv_bfloat16 sB[3][128*32];

    const int tid  = threadIdx.x;
    const int wid  = tid >> 5, lane = tid & 31;
    const int wm   = wid & 1,  wn   = wid >> 1;      // 2x4 warp grid
    const int bn   = blockIdx.x, bm = blockIdx.y;
    const int NCH  = KT / 32;                        // 96 chunks
    const uint32_t STB = 128 * 64;                   // stage bytes = 8192

    const char* Ab = (const char*)(A3 + (size_t)bm * 128 * KT);
    const char* Bb = (const char*)(B3 + (size_t)bn * 128 * KT);

    const uint32_t sA0 = smem_u32(&sA[0][0]);
    const uint32_t sB0 = smem_u32(&sB[0][0]);

    float acc[4][4][4];
#pragma unroll
    for (int i = 0; i < 4; i++)
#pragma unroll
        for (int j = 0; j < 4; j++)
#pragma unroll
            for (int k = 0; k < 4; k++) acc[i][j][k] = 0.f;

#define LOAD_TILE(c, st)                                                           \
    {                                                                              \
        int koff = (c) * 64;                                                       \
        _Pragma("unroll")                                                          \
        for (int i = 0; i < 2; i++) {                                              \
            int idx = tid + i * 256;                                               \
            int row = idx >> 2, seg = idx & 3;                                     \
            int pseg = seg ^ ((row >> 1) & 3);                                     \
            uint32_t so = (uint32_t)((st) * STB + row * 64 + pseg * 16);           \
            cp16(sA0 + so, Ab + (size_t)row * (KT*2) + koff + seg * 16);           \
            cp16(sB0 + so, Bb + (size_t)row * (KT*2) + koff + seg * 16);           \
        }                                                                          \
    }

    LOAD_TILE(0, 0); CP_COMMIT();
    LOAD_TILE(1, 1); CP_COMMIT();

    const int lrow = lane & 15;
    const int lhalf = lane >> 4;                     // 0/1 -> +16B column

    int st = 0;                                      // stage of chunk c
    for (int c = 0; c < NCH; c++) {
        CP_WAIT(1);                                  // stage of chunk c complete
        __syncthreads();                             // everyone done with c-1 too

        if (c + 2 < NCH) {
            int st2 = (st + 2 >= 3) ? st - 1 : st + 2;
            LOAD_TILE(c + 2, st2);
        }
        CP_COMMIT();

        uint32_t abase = sA0 + st * STB;
        uint32_t bbase = sB0 + st * STB;
#pragma unroll
        for (int kg = 0; kg < 2; kg++) {
            uint32_t a[4][4], b[2][4];
            int lseg = kg * 2 + lhalf;
#pragma unroll
            for (int mt = 0; mt < 4; mt++) {
                int row = wm*64 + mt*16 + lrow;
                ldsm4(a[mt], abase + (uint32_t)(row * 64 + (lseg ^ ((row >> 1) & 3)) * 16));
            }
#pragma unroll
            for (int p = 0; p < 2; p++) {
                int row = wn*32 + p*16 + lrow;
                ldsm4(b[p], bbase + (uint32_t)(row * 64 + (lseg ^ ((row >> 1) & 3)) * 16));
            }
#pragma unroll
            for (int mt = 0; mt < 4; mt++)
#pragma unroll
                for (int nt = 0; nt < 4; nt++) {
                    int p = nt >> 1, q = nt & 1;
                    mma16816(acc[mt][nt], a[mt], b[p][q], b[p][q + 2]);
                }
        }
        st = (st + 1 >= 3) ? 0 : st + 1;
    }

#pragma unroll
    for (int mt = 0; mt < 4; mt++) {
#pragma unroll
        for (int nt = 0; nt < 4; nt++) {
            int m0 = bm * 128 + wm * 64 + mt * 16 + (lane >> 2);
            int n0 = bn * 128 + wn * 32 + nt * 8 + 2 * (lane & 3);
            float c0 = acc[mt][nt][0], c1 = acc[mt][nt][1];
            float c2 = acc[mt][nt][2], c3 = acc[mt][nt][3];
            if (EPI == 0) {
                int part = n0 >> 10;
                __nv_bfloat16 *dh = (part == 0) ? g_Qh : (part == 1) ? g_Kh : g_Vh;
                __nv_bfloat16 *dl = (part == 0) ? g_Ql : (part == 1) ? g_Kl : g_Vl;
                float scl = (part == 0) ? 0.125f : 1.0f;
                int head = (n0 & 1023) >> 6, d = n0 & 63;
#pragma unroll
                for (int rr = 0; rr < 2; rr++) {
                    int m = m0 + rr * 8;
                    int bi = m >> 11, s = m & (SEQ - 1);
                    float v0 = (rr ? c2 : c0) * scl, v1 = (rr ? c3 : c1) * scl;
                    __nv_bfloat16 h0 = __float2bfloat16(v0);
                    __nv_bfloat16 l0 = __float2bfloat16(v0 - __bfloat162float(h0));
                    __nv_bfloat16 h1 = __float2bfloat16(v1);
                    __nv_bfloat16 l1 = __float2bfloat16(v1 - __bfloat162float(h1));
                    size_t idx = (((size_t)(bi*NH + head))*SEQ + s)*HD + d;
                    *(uint32_t*)&dh[idx] = pk2(h0, h1);
                    *(uint32_t*)&dl[idx] = pk2(l0, l1);
                }
            } else {
                float2 bv = *(const float2*)&bias[n0];
                *(float2*)&Cout[(size_t)m0 * DIM + n0]       = make_float2(c0 + bv.x, c1 + bv.y);
                *(float2*)&Cout[(size_t)(m0 + 8) * DIM + n0] = make_float2(c2 + bv.x, c3 + bv.y);
            }
        }
    }
}

// ---------------------------------------------------------------------------
// HMMA flash attention with cp.async 2-stage K/V pipeline.
// CTA = 64 queries x one (b,h), 4 warps. 32-key chunks, 128B rows with XOR
// swizzle (pseg = seg ^ (row&7)) -> conflict-free ldmatrix, 48KB static exact.
// QK^T: QhKh+QlKh+QhKl. PV: PhVh+PlVh+PhVl (P hi/lo built in registers).
// Output written as split-3 triplets into g_o3. Q pre-scaled by 1/8.
// ---------------------------------------------------------------------------
__global__ __launch_bounds__(128) void attn_mma()
{
    __shared__ __align__(16) __nv_bfloat16 sQh[64*64];       //  8192 B
    __shared__ __align__(16) __nv_bfloat16 sQl[64*64];       //  8192 B
    __shared__ __align__(16) __nv_bfloat16 sKh[2][32*64];    //  8192 B
    __shared__ __align__(16) __nv_bfloat16 sKl[2][32*64];    //  8192 B
    __shared__ __align__(16) __nv_bfloat16 sVh[2][32*64];    //  8192 B
    __shared__ __align__(16) __nv_bfloat16 sVl[2][32*64];    //  8192 B  => 49152 total

    const int qi  = blockIdx.x;
    const int bh  = blockIdx.y;
    const int b   = bh >> 4, h = bh & 15;
    const int tid = threadIdx.x, w = tid >> 5, lane = tid & 31;
    const int qbase = qi * 64;

    const size_t base = (size_t)bh * SEQ * HD;
    const uint32_t qh0 = smem_u32(sQh), ql0 = smem_u32(sQl);
    const uint32_t kh0 = smem_u32(sKh), kl0 = smem_u32(sKl);
    const uint32_t vh0 = smem_u32(sVh), vl0 = smem_u32(sVl);
    const uint32_t KVST = 32 * 128;                 // 4096 B per stage

    // Q tile via cp.async (64 rows x 128B, swizzled)
    for (int i = tid; i < 512; i += 128) {
        int r = i >> 3, seg = i & 7;
        int pseg = seg ^ (r & 7);
        const char* gq = (const char*)(g_Qh + base + (size_t)(qbase + r) * HD);
        const char* gl = (const char*)(g_Ql + base + (size_t)(qbase + r) * HD);
        cp16(qh0 + (uint32_t)(r * 128 + pseg * 16), gq + seg * 16);
        cp16(ql0 + (uint32_t)(r * 128 + pseg * 16), gl + seg * 16);
    }
    CP_COMMIT();

#define LOADKV(ch, st)                                                              \
    {                                                                               \
        int kb = (ch) * 32;                                                         \
        _Pragma("unroll")                                                           \
        for (int i = tid; i < 256; i += 128) {                                      \
            int r = i >> 3, seg = i & 7;                                            \
            int pseg = seg ^ (r & 7);                                               \
            size_t gidx = base + (size_t)(kb + r) * HD;                             \
            uint32_t so = (uint32_t)((st) * KVST + r * 128 + pseg * 16);            \
            cp16(kh0 + so, (const char*)(g_Kh + gidx) + seg * 16);                  \
            cp16(kl0 + so, (const char*)(g_Kl + gidx) + seg * 16);                  \
            cp16(vh0 + so, (const char*)(g_Vh + gidx) + seg * 16);                  \
            cp16(vl0 + so, (const char*)(g_Vl + gidx) + seg * 16);                  \
        }                                                                           \
    }

    const int nch = (qi < 4) ? 8 : 2 * (qi + 1);
    LOADKV(0, 0); CP_COMMIT();

    float o[8][4];
#pragma unroll
    for (int i = 0; i < 8; i++)
#pragma unroll
        for (int j = 0; j < 4; j++) o[i][j] = 0.f;
    float mi[2] = {-1e30f, -1e30f}, li[2] = {0.f, 0.f};

    const int lrow  = lane & 15;
    const int lhalf = lane >> 4;

    for (int ch = 0; ch < nch; ch++) {
        CP_WAIT(0);                      // Q (first iter) + K/V chunk ch ready
        __syncthreads();                 // and all warps done with prev stage
        if (ch + 1 < nch) { LOADKV(ch + 1, (ch + 1) & 1); }
        CP_COMMIT();

        const int kbase = ch * 32;
        const uint32_t kvoff = (uint32_t)((ch & 1) * KVST);

        // ---- S = Q K^T (3 split passes), 4 n-tiles of 8 keys ----
        float s[4][4];
#pragma unroll
        for (int nt = 0; nt < 4; nt++)
#pragma unroll
            for (int j = 0; j < 4; j++) s[nt][j] = 0.f;

#pragma unroll
        for (int kg = 0; kg < 4; kg++) {
            int lseg = kg * 2 + lhalf;
            uint32_t aH[4], aL[4], bH[2][4], bL[2][4];
            {
                int row = w*16 + lrow;
                uint32_t ao = (uint32_t)(row * 128 + (lseg ^ (row & 7)) * 16);
                ldsm4(aH, qh0 + ao);
                ldsm4(aL, ql0 + ao);
            }
#pragma unroll
            for (int p = 0; p < 2; p++) {
                int row = p*16 + lrow;
                uint32_t bo = kvoff + (uint32_t)(row * 128 + (lseg ^ (row & 7)) * 16);
                ldsm4(bH[p], kh0 + bo);
                ldsm4(bL[p], kl0 + bo);
            }
#pragma unroll
            for (int nt = 0; nt < 4; nt++) {
                int p = nt >> 1, q = nt & 1;
                mma16816(s[nt], aH, bH[p][q], bH[p][q+2]);
                mma16816(s[nt], aL, bH[p][q], bH[p][q+2]);
                mma16816(s[nt], aH, bL[p][q], bL[p][q+2]);
            }
        }

        // ---- causal mask (only near-diagonal chunks outside prefix) ----
        if (kbase >= PREFIX && kbase + 31 > qbase) {
            int q0 = qbase + w*16 + (lane >> 2);
#pragma unroll
            for (int nt = 0; nt < 4; nt++) {
                int k0 = kbase + nt*8 + 2*(lane & 3);
                if (k0     > q0)     s[nt][0] = -1e30f;
                if (k0 + 1 > q0)     s[nt][1] = -1e30f;
                if (k0     > q0 + 8) s[nt][2] = -1e30f;
                if (k0 + 1 > q0 + 8) s[nt][3] = -1e30f;
            }
        }

        // ---- online softmax (rows r and r+8), quad shfl reductions ----
#pragma unroll
        for (int rr = 0; rr < 2; rr++) {
            float mx = -1e30f;
#pragma unroll
            for (int nt = 0; nt < 4; nt++)
                mx = fmaxf(mx, fmaxf(s[nt][2*rr], s[nt][2*rr+1]));
            mx = fmaxf(mx, __shfl_xor_sync(0xffffffffu, mx, 1));
            mx = fmaxf(mx, __shfl_xor_sync(0xffffffffu, mx, 2));
            float mnew  = fmaxf(mi[rr], mx);
            float alpha = __expf(mi[rr] - mnew);
            float rs = 0.f;
#pragma unroll
            for (int nt = 0; nt < 4; nt++) {
                float p0 = __expf(s[nt][2*rr]   - mnew);
                float p1 = __expf(s[nt][2*rr+1] - mnew);
                s[nt][2*rr] = p0; s[nt][2*rr+1] = p1;
                rs += p0 + p1;
            }
            rs += __shfl_xor_sync(0xffffffffu, rs, 1);
            rs += __shfl_xor_sync(0xffffffffu, rs, 2);
            li[rr] = li[rr] * alpha + rs;
            mi[rr] = mnew;
#pragma unroll
            for (int dn = 0; dn < 8; dn++) {
                o[dn][2*rr] *= alpha; o[dn][2*rr+1] *= alpha;
            }
        }

        // ---- O += P V (3 split passes); P frags built in registers ----
#pragma unroll
        for (int kt = 0; kt < 2; kt++) {
            uint32_t pH[4], pL[4];
#pragma unroll
            for (int half = 0; half < 2; half++) {
                float* sv = s[2*kt + half];
                __nv_bfloat16 h0 = __float2bfloat16(sv[0]);
                __nv_bfloat16 h1 = __float2bfloat16(sv[1]);
                __nv_bfloat16 h2 = __float2bfloat16(sv[2]);
                __nv_bfloat16 h3 = __float2bfloat16(sv[3]);
                __nv_bfloat16 l0 = __float2bfloat16(sv[0] - __bfloat162float(h0));
                __nv_bfloat16 l1 = __float2bfloat16(sv[1] - __bfloat162float(h1));
                __nv_bfloat16 l2 = __float2bfloat16(sv[2] - __bfloat162float(h2));
                __nv_bfloat16 l3 = __float2bfloat16(sv[3] - __bfloat162float(h3));
                pH[half*2+0] = pk2(h0, h1); pH[half*2+1] = pk2(h2, h3);
                pL[half*2+0] = pk2(l0, l1); pL[half*2+1] = pk2(l2, l3);
            }
#pragma unroll
            for (int p4 = 0; p4 < 4; p4++) {
                int row = kt*16 + lrow;
                int lseg = p4*2 + lhalf;
                uint32_t vo = kvoff + (uint32_t)(row * 128 + (lseg ^ (row & 7)) * 16);
                uint32_t vH[4], vL[4];
                ldsm4t(vH, vh0 + vo);
                ldsm4t(vL, vl0 + vo);
                mma16816(o[2*p4],   pH, vH[0], vH[1]);
                mma16816(o[2*p4],   pL, vH[0], vH[1]);
                mma16816(o[2*p4],   pH, vL[0], vL[1]);
                mma16816(o[2*p4+1], pH, vH[2], vH[3]);
                mma16816(o[2*p4+1], pL, vH[2], vH[3]);
                mma16816(o[2*p4+1], pH, vL[2], vL[3]);
            }
        }
    }

    // ---- epilogue: normalize, split-3, write g_o3 triplets [hi,lo,hi] ----
#pragma unroll
    for (int dn = 0; dn < 8; dn++) {
        int d0 = dn*8 + 2*(lane & 3);
#pragma unroll
        for (int rr = 0; rr < 2; rr++) {
            int row = qbase + w*16 + (lane >> 2) + rr*8;
            float inv = 1.0f / li[rr];
            float v0 = o[dn][2*rr]   * inv;
            float v1 = o[dn][2*rr+1] * inv;
            __nv_bfloat16 h0 = __float2bfloat16(v0);
            __nv_bfloat16 l0 = __float2bfloat16(v0 - __bfloat162float(h0));
            __nv_bfloat16 h1 = __float2bfloat16(v1);
            __nv_bfloat16 l1 = __float2bfloat16(v1 - __bfloat162float(h1));
            size_t off = (size_t)(b*SEQ + row) * KT + (size_t)3 * (h*HD + d0);
            *(uint32_t*)&g_o3[off]     = pk2(h0, l0);
            *(uint32_t*)&g_o3[off + 2] = pk2(h0, h1);
            *(uint32_t*)&g_o3[off + 4] = pk2(l1, h1);
        }
    }
}

// ---------------------------------------------------------------------------
extern "C" void kernel_launch(void* const* d_in, const int* in_sizes, int n_in,
                              void* d_out, int out_size)
{
    const float* x      = (const float*)d_in[0];
    const float* qkv_w  = (const float*)d_in[1];
    const float* proj_w = (const float*)d_in[2];
    const float* proj_b = (const float*)d_in[3];
    float*       out    = (float*)d_out;

    void *px3, *pw3, *po3, *ppw3;
    cudaGetSymbolAddress(&px3,  g_x3);
    cudaGetSymbolAddress(&pw3,  g_w3);
    cudaGetSymbolAddress(&po3,  g_o3);
    cudaGetSymbolAddress(&ppw3, g_pw3);

    split3_kernel<0><<<(MROWS*DIM/4 + 255)/256, 256>>>(x,     (__nv_bfloat16*)px3,  MROWS*DIM/4);
    split3_kernel<1><<<(3*DIM*DIM/4 + 255)/256, 256>>>(qkv_w, (__nv_bfloat16*)pw3,  3*DIM*DIM/4);
    split3_kernel<1><<<(DIM*DIM/4   + 255)/256, 256>>>(proj_w,(__nv_bfloat16*)ppw3, DIM*DIM/4);

    mma_gemm<0><<<dim3(3*DIM/128, MROWS/128), 256>>>(
        (const __nv_bfloat16*)px3, (const __nv_bfloat16*)pw3, nullptr, nullptr);

    attn_mma<<<dim3(SEQ/64, BS*NH), 128>>>();

    mma_gemm<1><<<dim3(DIM/128, MROWS/128), 256>>>(
        (const __nv_bfloat16*)po3, (const __nv_bfloat16*)ppw3, proj_b, out);
}